// round 2
// baseline (speedup 1.0000x reference)
#include <cuda_runtime.h>
#include <math.h>

#define B_  32
#define T_  2048
#define D_  1024            // DQ = DV = UNITS
#define M_  (B_ * T_)       // 65536 rows of the big GEMM

#define BM 128
#define BN 128
#define BK 8
#define NKT (D_ / BK)       // 128 k-steps
#define NTILES (D_ / BN)    // 8 n-tiles

// ---- scratch (no allocation allowed; static device globals) ----
__device__ float g_qb[B_ * D_];                 // 128 KB: query proj + folded biases
__device__ float g_scorepart[NTILES * M_];      // 2 MB: per-n-tile score partials
__device__ float g_ctxpart[8 * B_ * D_];        // 1 MB: per-t-chunk context partials

// ============================================================================
// K1: qb[b][u] = query[b,:]·Wh[:,u] + bh[u] + bs[u] + bc[u]   (biases folded)
// ============================================================================
__global__ void qproj_kernel(const float* __restrict__ query,
                             const float* __restrict__ Wh,
                             const float* __restrict__ bh,
                             const float* __restrict__ bs,
                             const float* __restrict__ bc) {
    int g = blockIdx.x * blockDim.x + threadIdx.x;   // 32768 threads
    int u = g & (D_ - 1);
    int b = g >> 10;
    float acc = bh[u] + bs[u] + bc[u];
    const float* q = query + (size_t)b * D_;
    #pragma unroll 8
    for (int k = 0; k < D_; ++k)
        acc = fmaf(q[k], Wh[(size_t)k * D_ + u], acc);
    g_qb[(size_t)b * D_ + u] = acc;
}

// ============================================================================
// K2: fused score GEMM.
//   act[m][n] = values[m,:]·Ws[:,n]  (m = b*T + t)
//   partial[ntile][m] = sum_{n in tile} tanh(act + qb[b][n] + pc[b][t]*Wc[n]) * Vw[n]
// 128x128 tile, 8x8 per thread (split 4+4 quadrants), double-buffered smem.
// ============================================================================
__global__ __launch_bounds__(256, 2)
void score_gemm_kernel(const float* __restrict__ values,
                       const float* __restrict__ prev_cov,
                       const float* __restrict__ Ws,
                       const float* __restrict__ Wc,
                       const float* __restrict__ Vw) {
    __shared__ float As[2][BK][BM];
    __shared__ float Bs[2][BK][BN];
    __shared__ float Red[BM][17];    // padded, conflict-free reduce

    const int tid = threadIdx.x;
    const int tx  = tid & 15;
    const int ty  = tid >> 4;
    const int m0  = blockIdx.y * BM;
    const int n0  = blockIdx.x * BN;
    const int b   = blockIdx.y >> 4;          // T_/BM = 16 m-tiles per batch

    // global->smem load coords
    const int a_row = tid >> 1;               // 0..127
    const int a_k   = (tid & 1) * 4;          // 0 or 4
    const int b_row = tid >> 5;               // 0..7
    const int b_col = (tid & 31) * 4;         // 0..124

    const float* Aptr = values + (size_t)(m0 + a_row) * D_ + a_k;
    const float* Bptr = Ws + (size_t)b_row * D_ + n0 + b_col;

    float acc[8][8];
    #pragma unroll
    for (int i = 0; i < 8; ++i)
        #pragma unroll
        for (int j = 0; j < 8; ++j) acc[i][j] = 0.0f;

    // preload tile 0
    {
        float4 av = *(const float4*)(Aptr);
        float4 bv = *(const float4*)(Bptr);
        As[0][a_k + 0][a_row] = av.x;
        As[0][a_k + 1][a_row] = av.y;
        As[0][a_k + 2][a_row] = av.z;
        As[0][a_k + 3][a_row] = av.w;
        *(float4*)&Bs[0][b_row][b_col] = bv;
    }
    __syncthreads();

    for (int kt = 0; kt < NKT; ++kt) {
        const int buf = kt & 1;
        float4 an, bn;
        const bool more = (kt + 1 < NKT);
        if (more) {
            an = *(const float4*)(Aptr + (kt + 1) * BK);
            bn = *(const float4*)(Bptr + (size_t)(kt + 1) * BK * D_);
        }
        #pragma unroll
        for (int kk = 0; kk < BK; ++kk) {
            float4 a0 = *(const float4*)&As[buf][kk][ty * 4];
            float4 a1 = *(const float4*)&As[buf][kk][64 + ty * 4];
            float4 b0 = *(const float4*)&Bs[buf][kk][tx * 4];
            float4 b1 = *(const float4*)&Bs[buf][kk][64 + tx * 4];
            float ar[8] = {a0.x, a0.y, a0.z, a0.w, a1.x, a1.y, a1.z, a1.w};
            float br[8] = {b0.x, b0.y, b0.z, b0.w, b1.x, b1.y, b1.z, b1.w};
            #pragma unroll
            for (int i = 0; i < 8; ++i)
                #pragma unroll
                for (int j = 0; j < 8; ++j)
                    acc[i][j] = fmaf(ar[i], br[j], acc[i][j]);
        }
        if (more) {
            const int nb = buf ^ 1;
            As[nb][a_k + 0][a_row] = an.x;
            As[nb][a_k + 1][a_row] = an.y;
            As[nb][a_k + 2][a_row] = an.z;
            As[nb][a_k + 3][a_row] = an.w;
            *(float4*)&Bs[nb][b_row][b_col] = bn;
            __syncthreads();
        }
    }

    // ---- epilogue: + qb + pc*Wc, tanh, *Vw, reduce over this n-tile ----
    int mloc[8], nloc[8];
    #pragma unroll
    for (int i = 0; i < 8; ++i) {
        mloc[i] = (i < 4) ? (ty * 4 + i) : (64 + ty * 4 + (i - 4));
        nloc[i] = (i < 4) ? (tx * 4 + i) : (64 + tx * 4 + (i - 4));
    }
    float wc[8], vw[8], qbv[8];
    #pragma unroll
    for (int j = 0; j < 8; ++j) {
        int n = n0 + nloc[j];
        wc[j]  = Wc[n];
        vw[j]  = Vw[n];
        qbv[j] = g_qb[(size_t)b * D_ + n];
    }
    const float* pc = prev_cov + (size_t)b * T_;
    #pragma unroll
    for (int i = 0; i < 8; ++i) {
        int m = m0 + mloc[i];
        int t = m & (T_ - 1);
        float p = pc[t];
        float s = 0.0f;
        #pragma unroll
        for (int j = 0; j < 8; ++j) {
            float act = acc[i][j] + qbv[j] + p * wc[j];
            s += tanhf(act) * vw[j];
        }
        Red[mloc[i]][tx] = s;
    }
    __syncthreads();
    if (tid < BM) {
        float s = 0.0f;
        #pragma unroll
        for (int x = 0; x < 16; ++x) s += Red[tid][x];
        g_scorepart[(size_t)blockIdx.x * M_ + m0 + tid] = s;
    }
}

// ============================================================================
// K3: per-batch softmax over T; writes attention_weights + coverage to d_out
// ============================================================================
__global__ void softmax_kernel(const float* __restrict__ prev_cov,
                               const float* __restrict__ Vb,
                               float* __restrict__ out) {
    __shared__ float sc[T_];        // 8 KB
    __shared__ float red[256];
    const int b = blockIdx.x;
    const int tid = threadIdx.x;
    const float vb = Vb[0];

    float lmax = -1e30f;
    for (int t = tid; t < T_; t += 256) {
        float s = vb;
        #pragma unroll
        for (int nt = 0; nt < NTILES; ++nt)
            s += g_scorepart[(size_t)nt * M_ + (size_t)b * T_ + t];
        sc[t] = s;
        lmax = fmaxf(lmax, s);
    }
    red[tid] = lmax;
    __syncthreads();
    for (int st = 128; st > 0; st >>= 1) {
        if (tid < st) red[tid] = fmaxf(red[tid], red[tid + st]);
        __syncthreads();
    }
    const float mx = red[0];
    __syncthreads();

    float lsum = 0.0f;
    for (int t = tid; t < T_; t += 256) {
        float e = expf(sc[t] - mx);
        sc[t] = e;
        lsum += e;
    }
    red[tid] = lsum;
    __syncthreads();
    for (int st = 128; st > 0; st >>= 1) {
        if (tid < st) red[tid] += red[tid + st];
        __syncthreads();
    }
    const float inv = 1.0f / red[0];

    float* aw_out  = out + B_ * D_;               // [B,T] at offset 32768
    float* cov_out = out + B_ * D_ + B_ * T_;     // [B,T,1] at offset 98304
    const float* pc = prev_cov + (size_t)b * T_;
    for (int t = tid; t < T_; t += 256) {
        float a = sc[t] * inv;
        aw_out[(size_t)b * T_ + t]  = a;
        cov_out[(size_t)b * T_ + t] = a + pc[t];
    }
}

// ============================================================================
// K4a: context partials. grid (8 t-chunks, 32 b), 256 threads = 1024 d (float4)
// ============================================================================
__global__ void ctx_part_kernel(const float* __restrict__ values,
                                const float* __restrict__ aw) {
    const int tc = blockIdx.x, b = blockIdx.y, tid = threadIdx.x;
    __shared__ float sa[256];
    const int t0 = tc * 256;
    sa[tid] = aw[(size_t)b * T_ + t0 + tid];
    __syncthreads();

    const float4* vp = (const float4*)(values) + ((size_t)b * T_ + t0) * (D_ / 4) + tid;
    float4 acc = make_float4(0.f, 0.f, 0.f, 0.f);
    #pragma unroll 4
    for (int t = 0; t < 256; ++t) {
        float4 v = vp[(size_t)t * (D_ / 4)];
        float a = sa[t];
        acc.x = fmaf(a, v.x, acc.x);
        acc.y = fmaf(a, v.y, acc.y);
        acc.z = fmaf(a, v.z, acc.z);
        acc.w = fmaf(a, v.w, acc.w);
    }
    ((float4*)g_ctxpart)[((size_t)tc * B_ + b) * (D_ / 4) + tid] = acc;
}

// K4b: deterministic reduce of context partials into d_out[0 .. B*DV)
__global__ void ctx_reduce_kernel(float* __restrict__ out) {
    int g = blockIdx.x * blockDim.x + threadIdx.x;   // 32768
    float s = 0.0f;
    #pragma unroll
    for (int tc = 0; tc < 8; ++tc)
        s += g_ctxpart[(size_t)tc * B_ * D_ + g];
    out[g] = s;
}

// ============================================================================
extern "C" void kernel_launch(void* const* d_in, const int* in_sizes, int n_in,
                              void* d_out, int out_size) {
    const float* query    = (const float*)d_in[0];
    const float* values   = (const float*)d_in[1];
    const float* prev_cov = (const float*)d_in[2];
    const float* Wh       = (const float*)d_in[3];
    const float* bh       = (const float*)d_in[4];
    const float* Ws       = (const float*)d_in[5];
    const float* bs       = (const float*)d_in[6];
    const float* Wc       = (const float*)d_in[7];
    const float* bc       = (const float*)d_in[8];
    const float* Vw       = (const float*)d_in[9];
    const float* Vb       = (const float*)d_in[10];
    float* out = (float*)d_out;

    qproj_kernel<<<(B_ * D_) / 256, 256>>>(query, Wh, bh, bs, bc);
    score_gemm_kernel<<<dim3(NTILES, M_ / BM), 256>>>(values, prev_cov, Ws, Wc, Vw);
    softmax_kernel<<<B_, 256>>>(prev_cov, Vb, out);
    ctx_part_kernel<<<dim3(8, B_), 256>>>(values, out + B_ * D_);
    ctx_reduce_kernel<<<(B_ * D_) / 256, 256>>>(out);
}

// round 5
// speedup vs baseline: 1.1102x; 1.1102x over previous
#include <cuda_runtime.h>
#include <cuda_bf16.h>
#include <math.h>
#include <stdint.h>

#define B_  32
#define T_  2048
#define D_  1024
#define M_  (B_ * T_)
#define NTILES 8            // n-tiles of 128
#define NCTX 16

// ---------------- scratch (static device globals; no allocation) ----------------
__device__ float g_qb[B_ * D_];
__device__ float g_scorepart[NTILES * M_];
__device__ float g_ctxpart[NCTX * B_ * D_];

// ============================================================================
// qproj: qb[b][u] = query[b,:]·Wh[:,u] + bh[u] + bs[u] + bc[u]
// ============================================================================
__global__ void qproj_kernel(const float* __restrict__ query,
                             const float* __restrict__ Wh,
                             const float* __restrict__ bh,
                             const float* __restrict__ bs,
                             const float* __restrict__ bc) {
    int g = blockIdx.x * blockDim.x + threadIdx.x;
    int u = g & (D_ - 1);
    int b = g >> 10;
    float acc = bh[u] + bs[u] + bc[u];
    const float* q = query + (size_t)b * D_;
    #pragma unroll 8
    for (int k = 0; k < D_; ++k)
        acc = fmaf(q[k], Wh[(size_t)k * D_ + u], acc);
    g_qb[(size_t)b * D_ + u] = acc;
}

// ============================================================================
// score GEMM via mma.sync bf16 (HMMA), fp32-accurate via hi/lo 3-term split.
// CTA tile 128M x 128N, K-chunk 32, double-buffered smem, reg-prefetch of
// next chunk's globals. Fused epilogue -> per-row score partial.
// ============================================================================
#define AP 40                       // smem pitch in bf16 elems (80 B)
#define CH_A  (128 * AP)            // 5120 bf16 = 10240 B per A tile
#define CH_B  (128 * AP)
#define BUF_ELEMS (4 * CH_A)        // Ahi|Alo|Bhi|Blo
#define O_AHI 0
#define O_ALO CH_A
#define O_BHI (2 * CH_A)
#define O_BLO (3 * CH_A)

__device__ __forceinline__ void mma16816(float* d, const uint32_t* a, const uint32_t* b) {
    asm volatile(
        "mma.sync.aligned.m16n8k16.row.col.f32.bf16.bf16.f32 "
        "{%0,%1,%2,%3}, {%4,%5,%6,%7}, {%8,%9}, {%0,%1,%2,%3};"
        : "+f"(d[0]), "+f"(d[1]), "+f"(d[2]), "+f"(d[3])
        : "r"(a[0]), "r"(a[1]), "r"(a[2]), "r"(a[3]), "r"(b[0]), "r"(b[1]));
}

__global__ __launch_bounds__(256)
void score_gemm_kernel(const float* __restrict__ values,
                       const float* __restrict__ Ws,
                       const float* __restrict__ prev_cov,
                       const float* __restrict__ Wc,
                       const float* __restrict__ Vw) {
    extern __shared__ __nv_bfloat16 sm[];
    __nv_bfloat16* buf[2] = { sm, sm + BUF_ELEMS };
    float* qb_s = (float*)(sm + 2 * BUF_ELEMS);          // 128
    float* wc_s = qb_s + 128;
    float* vw_s = qb_s + 256;
    float* pc_s = qb_s + 384;
    float (*Red)[5] = (float(*)[5])(qb_s + 512);         // [128][5]

    const int tid  = threadIdx.x;
    const int wid  = tid >> 5;
    const int lane = tid & 31;
    const int wm   = (wid >> 2) * 64;
    const int wn   = (wid & 3) * 32;

    const int m0 = blockIdx.y * 128;
    const int n0 = blockIdx.x * 128;
    const int b  = blockIdx.y >> 4;
    const int tt0 = (blockIdx.y & 15) * 128;

    // stage epilogue constants
    if (tid < 128) {
        qb_s[tid] = g_qb[(size_t)b * D_ + n0 + tid];
        wc_s[tid] = Wc[n0 + tid];
    } else {
        int i = tid - 128;
        vw_s[i] = Vw[n0 + i];
        pc_s[i] = prev_cov[(size_t)b * T_ + tt0 + i];
    }

    // ---- per-thread global load coords ----
    // A: 1024 float4 per chunk: row = idx>>3 (0..127), k = (idx&7)*4
    // B: 1024 float4 per chunk: r(k) = idx&31, n = (idx>>5)*4
    const int a_row = tid >> 1;               // hold idx = tid+256i -> row = idx>>3
    float4 ra[4], rb[4];

    #define LOAD_CHUNK(c) do {                                              \
        _Pragma("unroll")                                                   \
        for (int i = 0; i < 4; ++i) {                                       \
            int idx = tid + 256 * i;                                        \
            int row = idx >> 3, kf = idx & 7;                               \
            ra[i] = *(const float4*)(values + (size_t)(m0 + row) * D_ + (c) * 32 + kf * 4); \
            int r = idx & 31, nf = idx >> 5;                                \
            rb[i] = *(const float4*)(Ws + (size_t)((c) * 32 + r) * D_ + n0 + nf * 4); \
        }                                                                   \
    } while (0)

    #define STORE_CHUNK(bi) do {                                            \
        __nv_bfloat16* bp = buf[bi];                                        \
        _Pragma("unroll")                                                   \
        for (int i = 0; i < 4; ++i) {                                       \
            int idx = tid + 256 * i;                                        \
            int row = idx >> 3, kf = idx & 7;                               \
            float x[4] = {ra[i].x, ra[i].y, ra[i].z, ra[i].w};              \
            __nv_bfloat16 h[4], l[4];                                       \
            _Pragma("unroll")                                               \
            for (int j = 0; j < 4; ++j) {                                   \
                h[j] = __float2bfloat16(x[j]);                              \
                l[j] = __float2bfloat16(x[j] - __bfloat162float(h[j]));     \
            }                                                               \
            *(uint2*)&bp[O_AHI + row * AP + kf * 4] = *(uint2*)h;           \
            *(uint2*)&bp[O_ALO + row * AP + kf * 4] = *(uint2*)l;           \
            int r = idx & 31, nf = idx >> 5;                                \
            float y[4] = {rb[i].x, rb[i].y, rb[i].z, rb[i].w};              \
            _Pragma("unroll")                                               \
            for (int j = 0; j < 4; ++j) {                                   \
                __nv_bfloat16 bh = __float2bfloat16(y[j]);                  \
                bp[O_BHI + (nf * 4 + j) * AP + r] = bh;                     \
                bp[O_BLO + (nf * 4 + j) * AP + r] =                         \
                    __float2bfloat16(y[j] - __bfloat162float(bh));          \
            }                                                               \
        }                                                                   \
    } while (0)

    float acc[4][4][4];
    #pragma unroll
    for (int i = 0; i < 4; ++i)
        #pragma unroll
        for (int j = 0; j < 4; ++j)
            #pragma unroll
            for (int r = 0; r < 4; ++r) acc[i][j][r] = 0.0f;

    LOAD_CHUNK(0);
    STORE_CHUNK(0);
    __syncthreads();

    const int r4  = lane >> 2;
    const int kq2 = (lane & 3) * 2;

    for (int c = 0; c < 32; ++c) {
        const bool more = (c + 1 < 32);
        if (more) LOAD_CHUNK(c + 1);

        const __nv_bfloat16* bp = buf[c & 1];
        #pragma unroll
        for (int kk = 0; kk < 32; kk += 16) {
            uint32_t ah[4][4], al[4][4], bh[4][2], bl[4][2];
            #pragma unroll
            for (int mf = 0; mf < 4; ++mf) {
                int rA = wm + mf * 16 + r4;
                int k0 = kk + kq2;
                ah[mf][0] = *(const uint32_t*)&bp[O_AHI + rA * AP + k0];
                ah[mf][1] = *(const uint32_t*)&bp[O_AHI + (rA + 8) * AP + k0];
                ah[mf][2] = *(const uint32_t*)&bp[O_AHI + rA * AP + k0 + 8];
                ah[mf][3] = *(const uint32_t*)&bp[O_AHI + (rA + 8) * AP + k0 + 8];
                al[mf][0] = *(const uint32_t*)&bp[O_ALO + rA * AP + k0];
                al[mf][1] = *(const uint32_t*)&bp[O_ALO + (rA + 8) * AP + k0];
                al[mf][2] = *(const uint32_t*)&bp[O_ALO + rA * AP + k0 + 8];
                al[mf][3] = *(const uint32_t*)&bp[O_ALO + (rA + 8) * AP + k0 + 8];
            }
            #pragma unroll
            for (int nf = 0; nf < 4; ++nf) {
                int rB = wn + nf * 8 + r4;
                int k0 = kk + kq2;
                bh[nf][0] = *(const uint32_t*)&bp[O_BHI + rB * AP + k0];
                bh[nf][1] = *(const uint32_t*)&bp[O_BHI + rB * AP + k0 + 8];
                bl[nf][0] = *(const uint32_t*)&bp[O_BLO + rB * AP + k0];
                bl[nf][1] = *(const uint32_t*)&bp[O_BLO + rB * AP + k0 + 8];
            }
            #pragma unroll
            for (int mf = 0; mf < 4; ++mf)
                #pragma unroll
                for (int nf = 0; nf < 4; ++nf) {
                    mma16816(acc[mf][nf], ah[mf], bh[nf]);   // hi*hi
                    mma16816(acc[mf][nf], ah[mf], bl[nf]);   // hi*lo
                    mma16816(acc[mf][nf], al[mf], bh[nf]);   // lo*hi
                }
        }

        if (more) {
            STORE_CHUNK((c + 1) & 1);
            __syncthreads();
        }
    }

    // ---- fused epilogue: tanh(act + qb + pc*Wc)·Vw, reduce over n ----
    #pragma unroll
    for (int mf = 0; mf < 4; ++mf) {
        int rowA = wm + mf * 16 + r4;
        int rowB = rowA + 8;
        float pA = pc_s[rowA], pB = pc_s[rowB];
        float sA = 0.0f, sB = 0.0f;
        #pragma unroll
        for (int nf = 0; nf < 4; ++nf) {
            int c0 = wn + nf * 8 + kq2;
            int c1 = c0 + 1;
            sA += tanhf(acc[mf][nf][0] + qb_s[c0] + pA * wc_s[c0]) * vw_s[c0];
            sA += tanhf(acc[mf][nf][1] + qb_s[c1] + pA * wc_s[c1]) * vw_s[c1];
            sB += tanhf(acc[mf][nf][2] + qb_s[c0] + pB * wc_s[c0]) * vw_s[c0];
            sB += tanhf(acc[mf][nf][3] + qb_s[c1] + pB * wc_s[c1]) * vw_s[c1];
        }
        sA += __shfl_xor_sync(0xffffffff, sA, 1);
        sA += __shfl_xor_sync(0xffffffff, sA, 2);
        sB += __shfl_xor_sync(0xffffffff, sB, 1);
        sB += __shfl_xor_sync(0xffffffff, sB, 2);
        if ((lane & 3) == 0) {
            Red[rowA][wid & 3] = sA;
            Red[rowB][wid & 3] = sB;
        }
    }
    __syncthreads();
    if (tid < 128) {
        float s = Red[tid][0] + Red[tid][1] + Red[tid][2] + Red[tid][3];
        g_scorepart[(size_t)blockIdx.x * M_ + m0 + tid] = s;
    }
}

#define GEMM_SMEM (2 * BUF_ELEMS * (int)sizeof(__nv_bfloat16) + 512 * (int)sizeof(float) + 128 * 5 * (int)sizeof(float))

// ============================================================================
// softmax over T per batch; writes attention_weights + coverage
// ============================================================================
__global__ void softmax_kernel(const float* __restrict__ prev_cov,
                               const float* __restrict__ Vb,
                               float* __restrict__ out) {
    __shared__ float sc[T_];
    __shared__ float red[256];
    const int b = blockIdx.x;
    const int tid = threadIdx.x;
    const float vb = Vb[0];

    float lmax = -1e30f;
    for (int t = tid; t < T_; t += 256) {
        float s = vb;
        #pragma unroll
        for (int nt = 0; nt < NTILES; ++nt)
            s += g_scorepart[(size_t)nt * M_ + (size_t)b * T_ + t];
        sc[t] = s;
        lmax = fmaxf(lmax, s);
    }
    red[tid] = lmax;
    __syncthreads();
    for (int st = 128; st > 0; st >>= 1) {
        if (tid < st) red[tid] = fmaxf(red[tid], red[tid + st]);
        __syncthreads();
    }
    const float mx = red[0];
    __syncthreads();

    float lsum = 0.0f;
    for (int t = tid; t < T_; t += 256) {
        float e = expf(sc[t] - mx);
        sc[t] = e;
        lsum += e;
    }
    red[tid] = lsum;
    __syncthreads();
    for (int st = 128; st > 0; st >>= 1) {
        if (tid < st) red[tid] += red[tid + st];
        __syncthreads();
    }
    const float inv = 1.0f / red[0];

    float* aw_out  = out + B_ * D_;
    float* cov_out = out + B_ * D_ + B_ * T_;
    const float* pc = prev_cov + (size_t)b * T_;
    for (int t = tid; t < T_; t += 256) {
        float a = sc[t] * inv;
        aw_out[(size_t)b * T_ + t]  = a;
        cov_out[(size_t)b * T_ + t] = a + pc[t];
    }
}

// ============================================================================
// context partials + reduce
// ============================================================================
__global__ void ctx_part_kernel(const float* __restrict__ values,
                                const float* __restrict__ aw) {
    const int tc = blockIdx.x, b = blockIdx.y, tid = threadIdx.x;
    __shared__ float sa[128];
    const int t0 = tc * 128;
    if (tid < 128) sa[tid] = aw[(size_t)b * T_ + t0 + tid];
    __syncthreads();

    const float4* vp = (const float4*)(values) + ((size_t)b * T_ + t0) * (D_ / 4) + tid;
    float4 acc = make_float4(0.f, 0.f, 0.f, 0.f);
    #pragma unroll 4
    for (int t = 0; t < 128; ++t) {
        float4 v = vp[(size_t)t * (D_ / 4)];
        float a = sa[t];
        acc.x = fmaf(a, v.x, acc.x);
        acc.y = fmaf(a, v.y, acc.y);
        acc.z = fmaf(a, v.z, acc.z);
        acc.w = fmaf(a, v.w, acc.w);
    }
    ((float4*)g_ctxpart)[((size_t)tc * B_ + b) * (D_ / 4) + tid] = acc;
}

__global__ void ctx_reduce_kernel(float* __restrict__ out) {
    int g = blockIdx.x * blockDim.x + threadIdx.x;
    float s = 0.0f;
    #pragma unroll
    for (int tc = 0; tc < NCTX; ++tc)
        s += g_ctxpart[(size_t)tc * B_ * D_ + g];
    out[g] = s;
}

// ============================================================================
extern "C" void kernel_launch(void* const* d_in, const int* in_sizes, int n_in,
                              void* d_out, int out_size) {
    const float* query    = (const float*)d_in[0];
    const float* values   = (const float*)d_in[1];
    const float* prev_cov = (const float*)d_in[2];
    const float* Wh       = (const float*)d_in[3];
    const float* bh       = (const float*)d_in[4];
    const float* Ws       = (const float*)d_in[5];
    const float* bs       = (const float*)d_in[6];
    const float* Wc       = (const float*)d_in[7];
    const float* bc       = (const float*)d_in[8];
    const float* Vw       = (const float*)d_in[9];
    const float* Vb       = (const float*)d_in[10];
    float* out = (float*)d_out;

    cudaFuncSetAttribute(score_gemm_kernel,
                         cudaFuncAttributeMaxDynamicSharedMemorySize, GEMM_SMEM);

    qproj_kernel<<<(B_ * D_) / 256, 256>>>(query, Wh, bh, bs, bc);
    score_gemm_kernel<<<dim3(NTILES, M_ / 128), 256, GEMM_SMEM>>>(values, Ws, prev_cov, Wc, Vw);
    softmax_kernel<<<B_, 256>>>(prev_cov, Vb, out);
    ctx_part_kernel<<<dim3(NCTX, B_), 256>>>(values, out + B_ * D_);
    ctx_reduce_kernel<<<(B_ * D_) / 256, 256>>>(out);
}

// round 6
// speedup vs baseline: 1.7111x; 1.5413x over previous
#include <cuda_runtime.h>
#include <cuda_bf16.h>
#include <math.h>
#include <stdint.h>

#define B_  32
#define T_  2048
#define D_  1024
#define M_  (B_ * T_)
#define NCTX 16
#define KS_  4

// ---------------- scratch (static device globals; no allocation) ----------------
__device__ __nv_bfloat16 g_vhi[(size_t)M_ * D_];     // 128 MB
__device__ __nv_bfloat16 g_vlo[(size_t)M_ * D_];     // 128 MB
__device__ __nv_bfloat16 g_wshi[(size_t)D_ * D_];    // Ws^T hi: [n][k]
__device__ __nv_bfloat16 g_wslo[(size_t)D_ * D_];    // Ws^T lo: [n][k]
__device__ float g_qpart[KS_ * B_ * D_];
__device__ float g_score[M_];
__device__ float g_ctxpart[NCTX * B_ * D_];

// ---------------- PTX helpers (base sm_80-level PTX; compiles for sm_103) ---
__device__ __forceinline__ uint32_t smem_u32(const void* p) {
    uint32_t a;
    asm("{ .reg .u64 t; cvta.to.shared.u64 t, %1; cvt.u32.u64 %0, t; }" : "=r"(a) : "l"(p));
    return a;
}
__device__ __forceinline__ void cp_async16(uint32_t dst, const void* src) {
    asm volatile("cp.async.cg.shared.global [%0], [%1], 16;" :: "r"(dst), "l"(src));
}
#define CP_COMMIT asm volatile("cp.async.commit_group;" ::: "memory")
#define CP_WAIT1  asm volatile("cp.async.wait_group 1;" ::: "memory")
#define CP_WAIT0  asm volatile("cp.async.wait_group 0;" ::: "memory")

__device__ __forceinline__ void ldsm4(uint32_t* r, uint32_t addr) {
    asm volatile("ldmatrix.sync.aligned.m8n8.x4.shared.b16 {%0,%1,%2,%3}, [%4];"
        : "=r"(r[0]), "=r"(r[1]), "=r"(r[2]), "=r"(r[3]) : "r"(addr));
}
__device__ __forceinline__ void mma16816(float* d, const uint32_t* a, uint32_t b0, uint32_t b1) {
    asm volatile(
        "mma.sync.aligned.m16n8k16.row.col.f32.bf16.bf16.f32 "
        "{%0,%1,%2,%3}, {%4,%5,%6,%7}, {%8,%9}, {%0,%1,%2,%3};"
        : "+f"(d[0]), "+f"(d[1]), "+f"(d[2]), "+f"(d[3])
        : "r"(a[0]), "r"(a[1]), "r"(a[2]), "r"(a[3]), "r"(b0), "r"(b1));
}

// ============================================================================
// conversions: f32 -> bf16 hi/lo split
// ============================================================================
__global__ void conv_values_kernel(const float* __restrict__ v) {
    size_t g = (size_t)blockIdx.x * 256 + threadIdx.x;   // float4 index
    float4 x = ((const float4*)v)[g];
    __nv_bfloat16 h0 = __float2bfloat16(x.x), h1 = __float2bfloat16(x.y);
    __nv_bfloat16 h2 = __float2bfloat16(x.z), h3 = __float2bfloat16(x.w);
    __nv_bfloat16 l0 = __float2bfloat16(x.x - __bfloat162float(h0));
    __nv_bfloat16 l1 = __float2bfloat16(x.y - __bfloat162float(h1));
    __nv_bfloat16 l2 = __float2bfloat16(x.z - __bfloat162float(h2));
    __nv_bfloat16 l3 = __float2bfloat16(x.w - __bfloat162float(h3));
    __nv_bfloat162 p;
    p.x = h0; p.y = h1; ((__nv_bfloat162*)g_vhi)[g * 2]     = p;
    p.x = h2; p.y = h3; ((__nv_bfloat162*)g_vhi)[g * 2 + 1] = p;
    p.x = l0; p.y = l1; ((__nv_bfloat162*)g_vlo)[g * 2]     = p;
    p.x = l2; p.y = l3; ((__nv_bfloat162*)g_vlo)[g * 2 + 1] = p;
}

__global__ void conv_ws_kernel(const float* __restrict__ Ws) {
    __shared__ float tile[32][33];
    const int n0 = blockIdx.x * 32, k0 = blockIdx.y * 32;
    const int tx = threadIdx.x, ty = threadIdx.y;     // (32, 8)
    #pragma unroll
    for (int i = 0; i < 32; i += 8)
        tile[ty + i][tx] = Ws[(size_t)(k0 + ty + i) * D_ + n0 + tx];
    __syncthreads();
    #pragma unroll
    for (int i = 0; i < 32; i += 8) {
        float x = tile[tx][ty + i];                   // Ws[k0+tx][n0+ty+i]
        __nv_bfloat16 h = __float2bfloat16(x);
        g_wshi[(size_t)(n0 + ty + i) * D_ + k0 + tx] = h;
        g_wslo[(size_t)(n0 + ty + i) * D_ + k0 + tx] = __float2bfloat16(x - __bfloat162float(h));
    }
}

// ============================================================================
// qproj partials (k-split x4); summed during GEMM epilogue staging
// ============================================================================
__global__ void qproj_part_kernel(const float* __restrict__ query,
                                  const float* __restrict__ Wh,
                                  const float* __restrict__ bh,
                                  const float* __restrict__ bs,
                                  const float* __restrict__ bc) {
    int g  = blockIdx.x * 256 + threadIdx.x;     // 32768
    int ks = blockIdx.y;
    int u = g & (D_ - 1);
    int b = g >> 10;
    float acc = (ks == 0) ? (bh[u] + bs[u] + bc[u]) : 0.0f;
    const float* q = query + (size_t)b * D_;
    int kbeg = ks * (D_ / KS_), kend = kbeg + D_ / KS_;
    #pragma unroll 8
    for (int k = kbeg; k < kend; ++k)
        acc = fmaf(q[k], Wh[(size_t)k * D_ + u], acc);
    g_qpart[(size_t)ks * B_ * D_ + g] = acc;
}

// ============================================================================
// score GEMM: CTA = 128M rows x full N (4 subtiles of 256); 8 warps 64x64.
// bf16 hi/lo 3-term split, cp.async double-buffered K-chunks of 32,
// ldmatrix fragment loads on XOR-swizzled 64B-pitch smem.
// Fused epilogue accumulates tanh(act+qb+pc*Wc)*Vw across ALL n -> g_score.
// ============================================================================
#define BUF_B 49152                 // AH 8K | AL 8K | BH 16K | BL 16K
#define O_AL  8192
#define O_B   16384
#define O_BL  16384                 // relative to O_B
#define EPI_OFF (2 * BUF_B)
#define GEMM_SMEM (EPI_OFF + (256 * 3 + 128 + 512) * 4)

__global__ __launch_bounds__(256, 1)
void score_gemm_kernel(const float* __restrict__ prev_cov,
                       const float* __restrict__ Wc,
                       const float* __restrict__ Vw) {
    extern __shared__ char smem[];
    const uint32_t sb = smem_u32(smem);
    float* qb_s = (float*)(smem + EPI_OFF);          // 256
    float* wc_s = qb_s + 256;
    float* vw_s = qb_s + 512;
    float* pc_s = qb_s + 768;                        // 128
    float (*Red)[4] = (float(*)[4])(qb_s + 896);     // [128][4]

    const int tid  = threadIdx.x;
    const int wid  = tid >> 5;
    const int lane = tid & 31;
    const int wm   = (wid >> 2) * 64;                // 0 / 64
    const int wn   = (wid & 3) * 64;                 // 0..192 within subtile

    const int m0  = blockIdx.x * 128;
    const int b   = blockIdx.x >> 4;
    const int tt0 = (blockIdx.x & 15) * 128;

    if (tid < 128) pc_s[tid] = prev_cov[(size_t)b * T_ + tt0 + tid];

    // per-lane fragment row precompute (A rows and B rows share formula)
    const int lr  = (lane & 7) + (lane & 8);         // row-in-16 block
    const int k8  = lane >> 4;                       // 0/1: k half
    uint32_t a_rb[4], a_pm[4], b_rb[4], b_pm[4];
    #pragma unroll
    for (int mf = 0; mf < 4; ++mf) {
        int r = wm + mf * 16 + lr;
        a_rb[mf] = r << 6; a_pm[mf] = (r >> 1) & 3;
    }
    #pragma unroll
    for (int p = 0; p < 4; ++p) {
        int n = wn + p * 16 + lr;
        b_rb[p] = n << 6; b_pm[p] = (n >> 1) & 3;
    }

    float sacc[4][2];
    #pragma unroll
    for (int mf = 0; mf < 4; ++mf) { sacc[mf][0] = 0.f; sacc[mf][1] = 0.f; }

    #define ISSUE_CHUNK(c, bi, ns) do {                                        \
        uint32_t bb_ = sb + (bi) * BUF_B;                                      \
        _Pragma("unroll")                                                      \
        for (int i_ = 0; i_ < 2; ++i_) {                                       \
            int idx_ = tid + 256 * i_; int r_ = idx_ >> 2, u_ = idx_ & 3;      \
            uint32_t d_ = bb_ + (r_ << 6) + (((u_ ^ ((r_ >> 1) & 3)) & 3) << 4); \
            size_t gsrc_ = (size_t)(m0 + r_) * D_ + (c) * 32 + u_ * 8;         \
            cp_async16(d_,        g_vhi + gsrc_);                              \
            cp_async16(d_ + O_AL, g_vlo + gsrc_);                              \
        }                                                                      \
        _Pragma("unroll")                                                      \
        for (int i_ = 0; i_ < 4; ++i_) {                                       \
            int idx_ = tid + 256 * i_; int r_ = idx_ >> 2, u_ = idx_ & 3;      \
            uint32_t d_ = bb_ + O_B + (r_ << 6) + (((u_ ^ ((r_ >> 1) & 3)) & 3) << 4); \
            size_t gsrc_ = (size_t)((ns) * 256 + r_) * D_ + (c) * 32 + u_ * 8; \
            cp_async16(d_,        g_wshi + gsrc_);                             \
            cp_async16(d_ + O_BL, g_wslo + gsrc_);                             \
        }                                                                      \
        CP_COMMIT;                                                             \
    } while (0)

    for (int ns = 0; ns < 4; ++ns) {
        // stage epilogue constants for this subtile
        {
            int n = ns * 256 + tid;
            float q = g_qpart[(size_t)b * D_ + n]
                    + g_qpart[(size_t)B_ * D_ + (size_t)b * D_ + n]
                    + g_qpart[(size_t)2 * B_ * D_ + (size_t)b * D_ + n]
                    + g_qpart[(size_t)3 * B_ * D_ + (size_t)b * D_ + n];
            qb_s[tid] = q;
            wc_s[tid] = Wc[n];
            vw_s[tid] = Vw[n];
        }

        float acc[4][8][4];
        #pragma unroll
        for (int i = 0; i < 4; ++i)
            #pragma unroll
            for (int j = 0; j < 8; ++j)
                #pragma unroll
                for (int r = 0; r < 4; ++r) acc[i][j][r] = 0.0f;

        ISSUE_CHUNK(0, 0, ns);
        for (int c = 0; c < 32; ++c) {
            const int bi = c & 1;
            if (c + 1 < 32) { ISSUE_CHUNK(c + 1, (c + 1) & 1, ns); CP_WAIT1; }
            else            { CP_WAIT0; }
            __syncthreads();

            const uint32_t bb = sb + bi * BUF_B;
            #pragma unroll
            for (int kk = 0; kk < 32; kk += 16) {
                const uint32_t ku = (kk >> 3) + k8;
                uint32_t ah[4][4], al[4][4];
                #pragma unroll
                for (int mf = 0; mf < 4; ++mf) {
                    uint32_t xo = (((ku ^ a_pm[mf]) & 3) << 4);
                    ldsm4(ah[mf], bb + a_rb[mf] + xo);
                    ldsm4(al[mf], bb + O_AL + a_rb[mf] + xo);
                }
                #pragma unroll
                for (int p = 0; p < 4; ++p) {
                    uint32_t xo = (((ku ^ b_pm[p]) & 3) << 4);
                    uint32_t bh[4], bl[4];
                    ldsm4(bh, bb + O_B + b_rb[p] + xo);
                    ldsm4(bl, bb + O_B + O_BL + b_rb[p] + xo);
                    #pragma unroll
                    for (int mf = 0; mf < 4; ++mf) {
                        mma16816(acc[mf][2 * p],     ah[mf], bh[0], bh[2]);
                        mma16816(acc[mf][2 * p],     ah[mf], bl[0], bl[2]);
                        mma16816(acc[mf][2 * p],     al[mf], bh[0], bh[2]);
                        mma16816(acc[mf][2 * p + 1], ah[mf], bh[1], bh[3]);
                        mma16816(acc[mf][2 * p + 1], ah[mf], bl[1], bl[3]);
                        mma16816(acc[mf][2 * p + 1], al[mf], bh[1], bh[3]);
                    }
                }
            }
            __syncthreads();
        }

        // fused epilogue for this subtile
        #pragma unroll
        for (int mf = 0; mf < 4; ++mf) {
            const int rA = wm + mf * 16 + (lane >> 2);
            const float pA = pc_s[rA], pB = pc_s[rA + 8];
            float sA = 0.f, sB = 0.f;
            #pragma unroll
            for (int nf = 0; nf < 8; ++nf) {
                int c0 = wn + nf * 8 + 2 * (lane & 3);
                int c1 = c0 + 1;
                sA += tanhf(acc[mf][nf][0] + qb_s[c0] + pA * wc_s[c0]) * vw_s[c0];
                sA += tanhf(acc[mf][nf][1] + qb_s[c1] + pA * wc_s[c1]) * vw_s[c1];
                sB += tanhf(acc[mf][nf][2] + qb_s[c0] + pB * wc_s[c0]) * vw_s[c0];
                sB += tanhf(acc[mf][nf][3] + qb_s[c1] + pB * wc_s[c1]) * vw_s[c1];
            }
            sacc[mf][0] += sA;
            sacc[mf][1] += sB;
        }
        __syncthreads();   // before next subtile overwrites qb_s/wc_s/vw_s
    }

    // reduce over lanes (n quads) and warps (n-warps), write final scores
    #pragma unroll
    for (int mf = 0; mf < 4; ++mf) {
        float sA = sacc[mf][0], sB = sacc[mf][1];
        sA += __shfl_xor_sync(0xffffffff, sA, 1);
        sA += __shfl_xor_sync(0xffffffff, sA, 2);
        sB += __shfl_xor_sync(0xffffffff, sB, 1);
        sB += __shfl_xor_sync(0xffffffff, sB, 2);
        if ((lane & 3) == 0) {
            int rA = wm + mf * 16 + (lane >> 2);
            Red[rA][wid & 3]     = sA;
            Red[rA + 8][wid & 3] = sB;
        }
    }
    __syncthreads();
    if (tid < 128) {
        g_score[(size_t)m0 + tid] = Red[tid][0] + Red[tid][1] + Red[tid][2] + Red[tid][3];
    }
}

// ============================================================================
// softmax over T per batch; writes attention_weights + coverage
// ============================================================================
__global__ void softmax_kernel(const float* __restrict__ prev_cov,
                               const float* __restrict__ Vb,
                               float* __restrict__ out) {
    __shared__ float sc[T_];
    __shared__ float red[256];
    const int b = blockIdx.x;
    const int tid = threadIdx.x;
    const float vb = Vb[0];

    float lmax = -1e30f;
    for (int t = tid; t < T_; t += 256) {
        float s = g_score[(size_t)b * T_ + t] + vb;
        sc[t] = s;
        lmax = fmaxf(lmax, s);
    }
    red[tid] = lmax;
    __syncthreads();
    for (int st = 128; st > 0; st >>= 1) {
        if (tid < st) red[tid] = fmaxf(red[tid], red[tid + st]);
        __syncthreads();
    }
    const float mx = red[0];
    __syncthreads();

    float lsum = 0.0f;
    for (int t = tid; t < T_; t += 256) {
        float e = expf(sc[t] - mx);
        sc[t] = e;
        lsum += e;
    }
    red[tid] = lsum;
    __syncthreads();
    for (int st = 128; st > 0; st >>= 1) {
        if (tid < st) red[tid] += red[tid + st];
        __syncthreads();
    }
    const float inv = 1.0f / red[0];

    float* aw_out  = out + B_ * D_;
    float* cov_out = out + B_ * D_ + B_ * T_;
    const float* pc = prev_cov + (size_t)b * T_;
    for (int t = tid; t < T_; t += 256) {
        float a = sc[t] * inv;
        aw_out[(size_t)b * T_ + t]  = a;
        cov_out[(size_t)b * T_ + t] = a + pc[t];
    }
}

// ============================================================================
// context partials + reduce
// ============================================================================
__global__ void ctx_part_kernel(const float* __restrict__ values,
                                const float* __restrict__ aw) {
    const int tc = blockIdx.x, b = blockIdx.y, tid = threadIdx.x;
    __shared__ float sa[128];
    const int t0 = tc * 128;
    if (tid < 128) sa[tid] = aw[(size_t)b * T_ + t0 + tid];
    __syncthreads();

    const float4* vp = (const float4*)(values) + ((size_t)b * T_ + t0) * (D_ / 4) + tid;
    float4 acc = make_float4(0.f, 0.f, 0.f, 0.f);
    #pragma unroll 4
    for (int t = 0; t < 128; ++t) {
        float4 v = vp[(size_t)t * (D_ / 4)];
        float a = sa[t];
        acc.x = fmaf(a, v.x, acc.x);
        acc.y = fmaf(a, v.y, acc.y);
        acc.z = fmaf(a, v.z, acc.z);
        acc.w = fmaf(a, v.w, acc.w);
    }
    ((float4*)g_ctxpart)[((size_t)tc * B_ + b) * (D_ / 4) + tid] = acc;
}

__global__ void ctx_reduce_kernel(float* __restrict__ out) {
    int g = blockIdx.x * blockDim.x + threadIdx.x;
    float s = 0.0f;
    #pragma unroll
    for (int tc = 0; tc < NCTX; ++tc)
        s += g_ctxpart[(size_t)tc * B_ * D_ + g];
    out[g] = s;
}

// ============================================================================
extern "C" void kernel_launch(void* const* d_in, const int* in_sizes, int n_in,
                              void* d_out, int out_size) {
    const float* query    = (const float*)d_in[0];
    const float* values   = (const float*)d_in[1];
    const float* prev_cov = (const float*)d_in[2];
    const float* Wh       = (const float*)d_in[3];
    const float* bh       = (const float*)d_in[4];
    const float* Ws       = (const float*)d_in[5];
    const float* bs       = (const float*)d_in[6];
    const float* Wc       = (const float*)d_in[7];
    const float* bc       = (const float*)d_in[8];
    const float* Vw       = (const float*)d_in[9];
    const float* Vb       = (const float*)d_in[10];
    float* out = (float*)d_out;

    cudaFuncSetAttribute(score_gemm_kernel,
                         cudaFuncAttributeMaxDynamicSharedMemorySize, GEMM_SMEM);

    conv_values_kernel<<<(int)((size_t)M_ * D_ / 4 / 256), 256>>>(values);
    conv_ws_kernel<<<dim3(32, 32), dim3(32, 8)>>>(Ws);
    qproj_part_kernel<<<dim3(128, KS_), 256>>>(query, Wh, bh, bs, bc);
    score_gemm_kernel<<<M_ / 128, 256, GEMM_SMEM>>>(prev_cov, Wc, Vw);
    softmax_kernel<<<B_, 256>>>(prev_cov, Vb, out);
    ctx_part_kernel<<<dim3(NCTX, B_), 256>>>(values, out + B_ * D_);
    ctx_reduce_kernel<<<(B_ * D_) / 256, 256>>>(out);
}

// round 7
// speedup vs baseline: 1.7155x; 1.0026x over previous
#include <cuda_runtime.h>
#include <cuda_bf16.h>
#include <math.h>
#include <stdint.h>

#define B_  32
#define T_  2048
#define D_  1024
#define M_  (B_ * T_)
#define NCTX 16
#define KS_  4

// ---------------- scratch (static device globals; no allocation) ----------------
__device__ __nv_bfloat16 g_vhi[(size_t)M_ * D_];     // 128 MB
__device__ __nv_bfloat16 g_vlo[(size_t)M_ * D_];     // 128 MB
__device__ __nv_bfloat16 g_wshi[(size_t)D_ * D_];    // Ws^T hi: [n][k]
__device__ __nv_bfloat16 g_wslo[(size_t)D_ * D_];    // Ws^T lo: [n][k]
__device__ float g_qpart[KS_ * B_ * D_];
__device__ float g_score[M_];
__device__ float g_ctxpart[NCTX * B_ * D_];

// ---------------- PTX helpers ----------------
__device__ __forceinline__ uint32_t smem_u32(const void* p) {
    uint32_t a;
    asm("{ .reg .u64 t; cvta.to.shared.u64 t, %1; cvt.u32.u64 %0, t; }" : "=r"(a) : "l"(p));
    return a;
}
__device__ __forceinline__ void cp_async16(uint32_t dst, const void* src) {
    asm volatile("cp.async.cg.shared.global [%0], [%1], 16;" :: "r"(dst), "l"(src));
}
#define CP_COMMIT asm volatile("cp.async.commit_group;" ::: "memory")
#define CP_WAIT1  asm volatile("cp.async.wait_group 1;" ::: "memory")
#define CP_WAIT0  asm volatile("cp.async.wait_group 0;" ::: "memory")

__device__ __forceinline__ void ldsm4(uint32_t* r, uint32_t addr) {
    asm volatile("ldmatrix.sync.aligned.m8n8.x4.shared.b16 {%0,%1,%2,%3}, [%4];"
        : "=r"(r[0]), "=r"(r[1]), "=r"(r[2]), "=r"(r[3]) : "r"(addr));
}
// NOTE: non-volatile — pure register op; lets ptxas schedule across MMAs.
__device__ __forceinline__ void mma16816(float* d, const uint32_t* a, uint32_t b0, uint32_t b1) {
    asm("mma.sync.aligned.m16n8k16.row.col.f32.bf16.bf16.f32 "
        "{%0,%1,%2,%3}, {%4,%5,%6,%7}, {%8,%9}, {%0,%1,%2,%3};"
        : "+f"(d[0]), "+f"(d[1]), "+f"(d[2]), "+f"(d[3])
        : "r"(a[0]), "r"(a[1]), "r"(a[2]), "r"(a[3]), "r"(b0), "r"(b1));
}

// ============================================================================
// conversions: f32 -> bf16 hi/lo split
// ============================================================================
__global__ void conv_values_kernel(const float* __restrict__ v) {
    size_t g = (size_t)blockIdx.x * 256 + threadIdx.x;   // float4 index
    float4 x = ((const float4*)v)[g];
    __nv_bfloat16 h0 = __float2bfloat16(x.x), h1 = __float2bfloat16(x.y);
    __nv_bfloat16 h2 = __float2bfloat16(x.z), h3 = __float2bfloat16(x.w);
    __nv_bfloat16 l0 = __float2bfloat16(x.x - __bfloat162float(h0));
    __nv_bfloat16 l1 = __float2bfloat16(x.y - __bfloat162float(h1));
    __nv_bfloat16 l2 = __float2bfloat16(x.z - __bfloat162float(h2));
    __nv_bfloat16 l3 = __float2bfloat16(x.w - __bfloat162float(h3));
    __nv_bfloat162 p;
    p.x = h0; p.y = h1; ((__nv_bfloat162*)g_vhi)[g * 2]     = p;
    p.x = h2; p.y = h3; ((__nv_bfloat162*)g_vhi)[g * 2 + 1] = p;
    p.x = l0; p.y = l1; ((__nv_bfloat162*)g_vlo)[g * 2]     = p;
    p.x = l2; p.y = l3; ((__nv_bfloat162*)g_vlo)[g * 2 + 1] = p;
}

__global__ void conv_ws_kernel(const float* __restrict__ Ws) {
    __shared__ float tile[32][33];
    const int n0 = blockIdx.x * 32, k0 = blockIdx.y * 32;
    const int tx = threadIdx.x, ty = threadIdx.y;     // (32, 8)
    #pragma unroll
    for (int i = 0; i < 32; i += 8)
        tile[ty + i][tx] = Ws[(size_t)(k0 + ty + i) * D_ + n0 + tx];
    __syncthreads();
    #pragma unroll
    for (int i = 0; i < 32; i += 8) {
        float x = tile[tx][ty + i];                   // Ws[k0+tx][n0+ty+i]
        __nv_bfloat16 h = __float2bfloat16(x);
        g_wshi[(size_t)(n0 + ty + i) * D_ + k0 + tx] = h;
        g_wslo[(size_t)(n0 + ty + i) * D_ + k0 + tx] = __float2bfloat16(x - __bfloat162float(h));
    }
}

// ============================================================================
// qproj partials (k-split x4); summed during GEMM epilogue staging
// ============================================================================
__global__ void qproj_part_kernel(const float* __restrict__ query,
                                  const float* __restrict__ Wh,
                                  const float* __restrict__ bh,
                                  const float* __restrict__ bs,
                                  const float* __restrict__ bc) {
    int g  = blockIdx.x * 256 + threadIdx.x;     // 32768
    int ks = blockIdx.y;
    int u = g & (D_ - 1);
    int b = g >> 10;
    float acc = (ks == 0) ? (bh[u] + bs[u] + bc[u]) : 0.0f;
    const float* q = query + (size_t)b * D_;
    int kbeg = ks * (D_ / KS_), kend = kbeg + D_ / KS_;
    #pragma unroll 8
    for (int k = kbeg; k < kend; ++k)
        acc = fmaf(q[k], Wh[(size_t)k * D_ + u], acc);
    g_qpart[(size_t)ks * B_ * D_ + g] = acc;
}

// ============================================================================
// score GEMM: CTA = 128M x full N (4 subtiles of 256); 8 warps, 64x64 each.
// bf16 hi/lo 3-term split; 3-stage cp.async pipeline (1 sync/chunk);
// ldmatrix on XOR-swizzled 64B-pitch smem with hoisted address math;
// non-volatile MMA + term-separated ordering for deep ILP.
// ============================================================================
#define BUF_B 49152                 // AH 8K | AL 8K | BH 16K | BL 16K
#define O_AL  8192
#define O_B   16384
#define O_BL  16384                 // relative to O_B
#define NSTAGE 3
#define EPI_OFF (NSTAGE * BUF_B)
#define GEMM_SMEM (EPI_OFF + (256 * 3 + 128 + 512) * 4)

__global__ __launch_bounds__(256, 1)
void score_gemm_kernel(const float* __restrict__ prev_cov,
                       const float* __restrict__ Wc,
                       const float* __restrict__ Vw) {
    extern __shared__ char smem[];
    const uint32_t sb = smem_u32(smem);
    float* qb_s = (float*)(smem + EPI_OFF);          // 256
    float* wc_s = qb_s + 256;
    float* vw_s = qb_s + 512;
    float* pc_s = qb_s + 768;                        // 128
    float (*Red)[4] = (float(*)[4])(qb_s + 896);     // [128][4]

    const int tid  = threadIdx.x;
    const int wid  = tid >> 5;
    const int lane = tid & 31;
    const int wm   = (wid >> 2) * 64;                // 0 / 64
    const int wn   = (wid & 3) * 64;                 // 0..192 within subtile

    const int m0  = blockIdx.x * 128;
    const int b   = blockIdx.x >> 4;
    const int tt0 = (blockIdx.x & 15) * 128;

    if (tid < 128) pc_s[tid] = prev_cov[(size_t)b * T_ + tt0 + tid];

    // ---- hoisted fragment addressing ----
    // row-in-16 block and k-half for ldmatrix lane mapping
    const int lr  = (lane & 7) + (lane & 8);
    const uint32_t k8 = lane >> 4;                   // 0/1
    // combined offsets (buffer-relative) for kk=0; kk=16 differs by ^0x20
    uint32_t aoff_h[4], aoff_l[4], boff_h[4], boff_l[4];
    #pragma unroll
    for (int mf = 0; mf < 4; ++mf) {
        int r = wm + mf * 16 + lr;
        uint32_t xo = (((k8 ^ (r >> 1)) & 3) << 4);
        aoff_h[mf] = (uint32_t)(r << 6) + xo;
        aoff_l[mf] = aoff_h[mf] + O_AL;
    }
    #pragma unroll
    for (int p = 0; p < 4; ++p) {
        int n = wn + p * 16 + lr;
        uint32_t xo = (((k8 ^ (n >> 1)) & 3) << 4);
        boff_h[p] = (uint32_t)(n << 6) + xo + O_B;
        boff_l[p] = boff_h[p] + O_BL;
    }

    float sacc[4][2];
    #pragma unroll
    for (int mf = 0; mf < 4; ++mf) { sacc[mf][0] = 0.f; sacc[mf][1] = 0.f; }

    #define ISSUE_CHUNK(c, bi, ns) do {                                        \
        uint32_t bb_ = sb + (bi) * BUF_B;                                      \
        _Pragma("unroll")                                                      \
        for (int i_ = 0; i_ < 2; ++i_) {                                       \
            int idx_ = tid + 256 * i_; int r_ = idx_ >> 2, u_ = idx_ & 3;      \
            uint32_t d_ = bb_ + (r_ << 6) + (((u_ ^ ((r_ >> 1) & 3)) & 3) << 4); \
            size_t gsrc_ = (size_t)(m0 + r_) * D_ + (c) * 32 + u_ * 8;         \
            cp_async16(d_,        g_vhi + gsrc_);                              \
            cp_async16(d_ + O_AL, g_vlo + gsrc_);                              \
        }                                                                      \
        _Pragma("unroll")                                                      \
        for (int i_ = 0; i_ < 4; ++i_) {                                       \
            int idx_ = tid + 256 * i_; int r_ = idx_ >> 2, u_ = idx_ & 3;      \
            uint32_t d_ = bb_ + O_B + (r_ << 6) + (((u_ ^ ((r_ >> 1) & 3)) & 3) << 4); \
            size_t gsrc_ = (size_t)((ns) * 256 + r_) * D_ + (c) * 32 + u_ * 8; \
            cp_async16(d_,        g_wshi + gsrc_);                             \
            cp_async16(d_ + O_BL, g_wslo + gsrc_);                             \
        }                                                                      \
        CP_COMMIT;                                                             \
    } while (0)

    for (int ns = 0; ns < 4; ++ns) {
        // stage epilogue constants for this subtile
        {
            int n = ns * 256 + tid;
            float q = g_qpart[(size_t)b * D_ + n]
                    + g_qpart[(size_t)B_ * D_ + (size_t)b * D_ + n]
                    + g_qpart[(size_t)2 * B_ * D_ + (size_t)b * D_ + n]
                    + g_qpart[(size_t)3 * B_ * D_ + (size_t)b * D_ + n];
            qb_s[tid] = q;
            wc_s[tid] = Wc[n];
            vw_s[tid] = Vw[n];
        }

        float acc[4][8][4];
        #pragma unroll
        for (int i = 0; i < 4; ++i)
            #pragma unroll
            for (int j = 0; j < 8; ++j)
                #pragma unroll
                for (int r = 0; r < 4; ++r) acc[i][j][r] = 0.0f;

        // 3-stage pipeline prologue
        ISSUE_CHUNK(0, 0, ns);
        ISSUE_CHUNK(1, 1, ns);

        for (int c = 0; c < 32; ++c) {
            if (c + 1 < 32) CP_WAIT1; else CP_WAIT0;   // chunk c resident
            __syncthreads();
            if (c + 2 < 32) ISSUE_CHUNK(c + 2, (c + 2) % NSTAGE, ns);

            const uint32_t bb = sb + (c % NSTAGE) * BUF_B;
            #pragma unroll
            for (int kk = 0; kk < 32; kk += 16) {
                const uint32_t xm = kk ? 0x20u : 0u;   // k-half toggles swizzle bit 5
                uint32_t ah[4][4], al[4][4];
                #pragma unroll
                for (int mf = 0; mf < 4; ++mf) {
                    ldsm4(ah[mf], (bb + aoff_h[mf]) ^ xm);
                    ldsm4(al[mf], (bb + aoff_l[mf]) ^ xm);
                }
                #pragma unroll
                for (int p = 0; p < 4; ++p) {
                    uint32_t bh[4], bl[4];
                    ldsm4(bh, (bb + boff_h[p]) ^ xm);
                    ldsm4(bl, (bb + boff_l[p]) ^ xm);
                    // term-separated: each accumulator revisited at distance 8
                    #pragma unroll
                    for (int mf = 0; mf < 4; ++mf) {
                        mma16816(acc[mf][2 * p],     ah[mf], bh[0], bh[2]);
                        mma16816(acc[mf][2 * p + 1], ah[mf], bh[1], bh[3]);
                    }
                    #pragma unroll
                    for (int mf = 0; mf < 4; ++mf) {
                        mma16816(acc[mf][2 * p],     ah[mf], bl[0], bl[2]);
                        mma16816(acc[mf][2 * p + 1], ah[mf], bl[1], bl[3]);
                    }
                    #pragma unroll
                    for (int mf = 0; mf < 4; ++mf) {
                        mma16816(acc[mf][2 * p],     al[mf], bh[0], bh[2]);
                        mma16816(acc[mf][2 * p + 1], al[mf], bh[1], bh[3]);
                    }
                }
            }
        }

        // fused epilogue for this subtile
        #pragma unroll
        for (int mf = 0; mf < 4; ++mf) {
            const int rA = wm + mf * 16 + (lane >> 2);
            const float pA = pc_s[rA], pB = pc_s[rA + 8];
            float sA = 0.f, sB = 0.f;
            #pragma unroll
            for (int nf = 0; nf < 8; ++nf) {
                int c0 = wn + nf * 8 + 2 * (lane & 3);
                int c1 = c0 + 1;
                sA += tanhf(acc[mf][nf][0] + qb_s[c0] + pA * wc_s[c0]) * vw_s[c0];
                sA += tanhf(acc[mf][nf][1] + qb_s[c1] + pA * wc_s[c1]) * vw_s[c1];
                sB += tanhf(acc[mf][nf][2] + qb_s[c0] + pB * wc_s[c0]) * vw_s[c0];
                sB += tanhf(acc[mf][nf][3] + qb_s[c1] + pB * wc_s[c1]) * vw_s[c1];
            }
            sacc[mf][0] += sA;
            sacc[mf][1] += sB;
        }
        __syncthreads();   // before next subtile overwrites qb_s/wc_s/vw_s
    }

    // reduce over lanes (n quads) and warps (n-warps), write final scores
    #pragma unroll
    for (int mf = 0; mf < 4; ++mf) {
        float sA = sacc[mf][0], sB = sacc[mf][1];
        sA += __shfl_xor_sync(0xffffffff, sA, 1);
        sA += __shfl_xor_sync(0xffffffff, sA, 2);
        sB += __shfl_xor_sync(0xffffffff, sB, 1);
        sB += __shfl_xor_sync(0xffffffff, sB, 2);
        if ((lane & 3) == 0) {
            int rA = wm + mf * 16 + (lane >> 2);
            Red[rA][wid & 3]     = sA;
            Red[rA + 8][wid & 3] = sB;
        }
    }
    __syncthreads();
    if (tid < 128) {
        g_score[(size_t)m0 + tid] = Red[tid][0] + Red[tid][1] + Red[tid][2] + Red[tid][3];
    }
}

// ============================================================================
// softmax over T per batch; writes attention_weights + coverage
// ============================================================================
__global__ void softmax_kernel(const float* __restrict__ prev_cov,
                               const float* __restrict__ Vb,
                               float* __restrict__ out) {
    __shared__ float sc[T_];
    __shared__ float red[256];
    const int b = blockIdx.x;
    const int tid = threadIdx.x;
    const float vb = Vb[0];

    float lmax = -1e30f;
    for (int t = tid; t < T_; t += 256) {
        float s = g_score[(size_t)b * T_ + t] + vb;
        sc[t] = s;
        lmax = fmaxf(lmax, s);
    }
    red[tid] = lmax;
    __syncthreads();
    for (int st = 128; st > 0; st >>= 1) {
        if (tid < st) red[tid] = fmaxf(red[tid], red[tid + st]);
        __syncthreads();
    }
    const float mx = red[0];
    __syncthreads();

    float lsum = 0.0f;
    for (int t = tid; t < T_; t += 256) {
        float e = expf(sc[t] - mx);
        sc[t] = e;
        lsum += e;
    }
    red[tid] = lsum;
    __syncthreads();
    for (int st = 128; st > 0; st >>= 1) {
        if (tid < st) red[tid] += red[tid + st];
        __syncthreads();
    }
    const float inv = 1.0f / red[0];

    float* aw_out  = out + B_ * D_;
    float* cov_out = out + B_ * D_ + B_ * T_;
    const float* pc = prev_cov + (size_t)b * T_;
    for (int t = tid; t < T_; t += 256) {
        float a = sc[t] * inv;
        aw_out[(size_t)b * T_ + t]  = a;
        cov_out[(size_t)b * T_ + t] = a + pc[t];
    }
}

// ============================================================================
// context partials + reduce
// ============================================================================
__global__ void ctx_part_kernel(const float* __restrict__ values,
                                const float* __restrict__ aw) {
    const int tc = blockIdx.x, b = blockIdx.y, tid = threadIdx.x;
    __shared__ float sa[128];
    const int t0 = tc * 128;
    if (tid < 128) sa[tid] = aw[(size_t)b * T_ + t0 + tid];
    __syncthreads();

    const float4* vp = (const float4*)(values) + ((size_t)b * T_ + t0) * (D_ / 4) + tid;
    float4 acc = make_float4(0.f, 0.f, 0.f, 0.f);
    #pragma unroll 4
    for (int t = 0; t < 128; ++t) {
        float4 v = vp[(size_t)t * (D_ / 4)];
        float a = sa[t];
        acc.x = fmaf(a, v.x, acc.x);
        acc.y = fmaf(a, v.y, acc.y);
        acc.z = fmaf(a, v.z, acc.z);
        acc.w = fmaf(a, v.w, acc.w);
    }
    ((float4*)g_ctxpart)[((size_t)tc * B_ + b) * (D_ / 4) + tid] = acc;
}

__global__ void ctx_reduce_kernel(float* __restrict__ out) {
    int g = blockIdx.x * blockDim.x + threadIdx.x;
    float s = 0.0f;
    #pragma unroll
    for (int tc = 0; tc < NCTX; ++tc)
        s += g_ctxpart[(size_t)tc * B_ * D_ + g];
    out[g] = s;
}

// ============================================================================
extern "C" void kernel_launch(void* const* d_in, const int* in_sizes, int n_in,
                              void* d_out, int out_size) {
    const float* query    = (const float*)d_in[0];
    const float* values   = (const float*)d_in[1];
    const float* prev_cov = (const float*)d_in[2];
    const float* Wh       = (const float*)d_in[3];
    const float* bh       = (const float*)d_in[4];
    const float* Ws       = (const float*)d_in[5];
    const float* bs       = (const float*)d_in[6];
    const float* Wc       = (const float*)d_in[7];
    const float* bc       = (const float*)d_in[8];
    const float* Vw       = (const float*)d_in[9];
    const float* Vb       = (const float*)d_in[10];
    float* out = (float*)d_out;

    cudaFuncSetAttribute(score_gemm_kernel,
                         cudaFuncAttributeMaxDynamicSharedMemorySize, GEMM_SMEM);

    conv_values_kernel<<<(int)((size_t)M_ * D_ / 4 / 256), 256>>>(values);
    conv_ws_kernel<<<dim3(32, 32), dim3(32, 8)>>>(Ws);
    qproj_part_kernel<<<dim3(128, KS_), 256>>>(query, Wh, bh, bs, bc);
    score_gemm_kernel<<<M_ / 128, 256, GEMM_SMEM>>>(prev_cov, Wc, Vw);
    softmax_kernel<<<B_, 256>>>(prev_cov, Vb, out);
    ctx_part_kernel<<<dim3(NCTX, B_), 256>>>(values, out + B_ * D_);
    ctx_reduce_kernel<<<(B_ * D_) / 256, 256>>>(out);
}

// round 8
// speedup vs baseline: 1.7537x; 1.0222x over previous
#include <cuda_runtime.h>
#include <cuda_bf16.h>
#include <math.h>
#include <stdint.h>

#define B_  32
#define T_  2048
#define D_  1024
#define M_  (B_ * T_)
#define NCTX 16
#define KS_  4

// ---------------- scratch (static device globals; no allocation) ----------------
__device__ __nv_bfloat16 g_vhi[(size_t)M_ * D_];     // 128 MB
__device__ __nv_bfloat16 g_vlo[(size_t)M_ * D_];     // 128 MB
__device__ __nv_bfloat16 g_wshi[(size_t)D_ * D_];    // Ws^T hi: [n][k]
__device__ __nv_bfloat16 g_wslo[(size_t)D_ * D_];    // Ws^T lo: [n][k]
__device__ float g_qpart[KS_ * B_ * D_];
__device__ float g_score[M_];
__device__ float g_ctxpart[NCTX * B_ * D_];

// ---------------- PTX helpers ----------------
__device__ __forceinline__ uint32_t smem_u32(const void* p) {
    uint32_t a;
    asm("{ .reg .u64 t; cvta.to.shared.u64 t, %1; cvt.u32.u64 %0, t; }" : "=r"(a) : "l"(p));
    return a;
}
__device__ __forceinline__ void cp_async16(uint32_t dst, const void* src) {
    asm volatile("cp.async.cg.shared.global [%0], [%1], 16;" :: "r"(dst), "l"(src));
}
#define CP_COMMIT asm volatile("cp.async.commit_group;" ::: "memory")
#define CP_WAIT1  asm volatile("cp.async.wait_group 1;" ::: "memory")
#define CP_WAIT0  asm volatile("cp.async.wait_group 0;" ::: "memory")

__device__ __forceinline__ void ldsm4(uint32_t* r, uint32_t addr) {
    asm volatile("ldmatrix.sync.aligned.m8n8.x4.shared.b16 {%0,%1,%2,%3}, [%4];"
        : "=r"(r[0]), "=r"(r[1]), "=r"(r[2]), "=r"(r[3]) : "r"(addr));
}
// non-volatile: pure register op, ptxas may schedule freely
__device__ __forceinline__ void mma16816(float* d, const uint32_t* a, uint32_t b0, uint32_t b1) {
    asm("mma.sync.aligned.m16n8k16.row.col.f32.bf16.bf16.f32 "
        "{%0,%1,%2,%3}, {%4,%5,%6,%7}, {%8,%9}, {%0,%1,%2,%3};"
        : "+f"(d[0]), "+f"(d[1]), "+f"(d[2]), "+f"(d[3])
        : "r"(a[0]), "r"(a[1]), "r"(a[2]), "r"(a[3]), "r"(b0), "r"(b1));
}

// ============================================================================
// conversions: f32 -> bf16 hi/lo split
// ============================================================================
__global__ void conv_values_kernel(const float* __restrict__ v) {
    size_t g = (size_t)blockIdx.x * 256 + threadIdx.x;   // float4 index
    float4 x = ((const float4*)v)[g];
    __nv_bfloat16 h0 = __float2bfloat16(x.x), h1 = __float2bfloat16(x.y);
    __nv_bfloat16 h2 = __float2bfloat16(x.z), h3 = __float2bfloat16(x.w);
    __nv_bfloat16 l0 = __float2bfloat16(x.x - __bfloat162float(h0));
    __nv_bfloat16 l1 = __float2bfloat16(x.y - __bfloat162float(h1));
    __nv_bfloat16 l2 = __float2bfloat16(x.z - __bfloat162float(h2));
    __nv_bfloat16 l3 = __float2bfloat16(x.w - __bfloat162float(h3));
    __nv_bfloat162 p;
    p.x = h0; p.y = h1; ((__nv_bfloat162*)g_vhi)[g * 2]     = p;
    p.x = h2; p.y = h3; ((__nv_bfloat162*)g_vhi)[g * 2 + 1] = p;
    p.x = l0; p.y = l1; ((__nv_bfloat162*)g_vlo)[g * 2]     = p;
    p.x = l2; p.y = l3; ((__nv_bfloat162*)g_vlo)[g * 2 + 1] = p;
}

__global__ void conv_ws_kernel(const float* __restrict__ Ws) {
    __shared__ float tile[32][33];
    const int n0 = blockIdx.x * 32, k0 = blockIdx.y * 32;
    const int tx = threadIdx.x, ty = threadIdx.y;     // (32, 8)
    #pragma unroll
    for (int i = 0; i < 32; i += 8)
        tile[ty + i][tx] = Ws[(size_t)(k0 + ty + i) * D_ + n0 + tx];
    __syncthreads();
    #pragma unroll
    for (int i = 0; i < 32; i += 8) {
        float x = tile[tx][ty + i];                   // Ws[k0+tx][n0+ty+i]
        __nv_bfloat16 h = __float2bfloat16(x);
        g_wshi[(size_t)(n0 + ty + i) * D_ + k0 + tx] = h;
        g_wslo[(size_t)(n0 + ty + i) * D_ + k0 + tx] = __float2bfloat16(x - __bfloat162float(h));
    }
}

// ============================================================================
// qproj partials (k-split x4); summed during GEMM epilogue staging
// ============================================================================
__global__ void qproj_part_kernel(const float* __restrict__ query,
                                  const float* __restrict__ Wh,
                                  const float* __restrict__ bh,
                                  const float* __restrict__ bs,
                                  const float* __restrict__ bc) {
    int g  = blockIdx.x * 256 + threadIdx.x;     // 32768
    int ks = blockIdx.y;
    int u = g & (D_ - 1);
    int b = g >> 10;
    float acc = (ks == 0) ? (bh[u] + bs[u] + bc[u]) : 0.0f;
    const float* q = query + (size_t)b * D_;
    int kbeg = ks * (D_ / KS_), kend = kbeg + D_ / KS_;
    #pragma unroll 8
    for (int k = kbeg; k < kend; ++k)
        acc = fmaf(q[k], Wh[(size_t)k * D_ + u], acc);
    g_qpart[(size_t)ks * B_ * D_ + g] = acc;
}

// ============================================================================
// score GEMM: CTA = 128M x 128N subtile (loop ns=0..7 covers N=1024).
// 8 warps, warp tile 64x32. 2 CTAs/SM (<=128 regs) for 4 warps/SMSP.
// bf16 hi/lo 3-term split with fragment-register reuse:
//   af=A_hi -> hh ; B_lo -> hl ; af=A_lo -> lh
// 3-stage cp.async pipeline, XOR-swizzled 64B-pitch smem, ldmatrix loads.
// ============================================================================
#define BUF_B 32768                 // AH 8K | AL 8K | BH 8K | BL 8K
#define O_AL  8192
#define O_BH  16384
#define O_BL  24576
#define NSTAGE 3
#define EPI_OFF (NSTAGE * BUF_B)    // 98304
#define GEMM_SMEM (EPI_OFF + (512 + 512) * 4)   // 102400

__global__ __launch_bounds__(256, 2)
void score_gemm_kernel(const float* __restrict__ prev_cov,
                       const float* __restrict__ Wc,
                       const float* __restrict__ Vw) {
    extern __shared__ char smem[];
    const uint32_t sb = smem_u32(smem);
    float* qb_s = (float*)(smem + EPI_OFF);          // 128
    float* wc_s = qb_s + 128;
    float* vw_s = qb_s + 256;
    float* pc_s = qb_s + 384;                        // 128
    float (*Red)[4] = (float(*)[4])(qb_s + 512);     // [128][4]

    const int tid  = threadIdx.x;
    const int wid  = tid >> 5;
    const int lane = tid & 31;
    const int wm   = (wid >> 2) * 64;                // 0 / 64
    const int wn   = (wid & 3) * 32;                 // 0..96

    const int m0  = blockIdx.x * 128;
    const int b   = blockIdx.x >> 4;
    const int tt0 = (blockIdx.x & 15) * 128;

    if (tid < 128) pc_s[tid] = prev_cov[(size_t)b * T_ + tt0 + tid];

    // ---- hoisted fragment addressing (kk=16 differs by ^0x20) ----
    const int lr  = (lane & 7) + (lane & 8);
    const uint32_t k8 = lane >> 4;                   // 0/1
    uint32_t aoff[4], boff[2];
    #pragma unroll
    for (int mf = 0; mf < 4; ++mf) {
        int r = wm + mf * 16 + lr;
        aoff[mf] = (uint32_t)(r << 6) + (((k8 ^ (r >> 1)) & 3) << 4);
    }
    #pragma unroll
    for (int p = 0; p < 2; ++p) {
        int n = wn + p * 16 + lr;
        boff[p] = (uint32_t)(n << 6) + (((k8 ^ (n >> 1)) & 3) << 4) + O_BH;
    }

    float sacc[4][2];
    #pragma unroll
    for (int mf = 0; mf < 4; ++mf) { sacc[mf][0] = 0.f; sacc[mf][1] = 0.f; }

    // per-chunk loads: A 8KB hi + 8KB lo (512 cp each), B same. 8 cp/thread.
    #define ISSUE_CHUNK(c, bi, ns) do {                                        \
        uint32_t bb_ = sb + (bi) * BUF_B;                                      \
        _Pragma("unroll")                                                      \
        for (int i_ = 0; i_ < 2; ++i_) {                                       \
            int idx_ = tid + 256 * i_; int r_ = idx_ >> 2, u_ = idx_ & 3;      \
            uint32_t d_ = bb_ + (r_ << 6) + (((u_ ^ ((r_ >> 1) & 3)) & 3) << 4); \
            size_t ga_ = (size_t)(m0 + r_) * D_ + (c) * 32 + u_ * 8;           \
            size_t gb_ = (size_t)((ns) * 128 + r_) * D_ + (c) * 32 + u_ * 8;   \
            cp_async16(d_,        g_vhi + ga_);                                \
            cp_async16(d_ + O_AL, g_vlo + ga_);                                \
            cp_async16(d_ + O_BH, g_wshi + gb_);                               \
            cp_async16(d_ + O_BL, g_wslo + gb_);                               \
        }                                                                      \
        CP_COMMIT;                                                             \
    } while (0)

    for (int ns = 0; ns < 8; ++ns) {
        // stage epilogue constants for this subtile
        if (tid < 128) {
            int n = ns * 128 + tid;
            float q = g_qpart[(size_t)b * D_ + n]
                    + g_qpart[(size_t)B_ * D_ + (size_t)b * D_ + n]
                    + g_qpart[(size_t)2 * B_ * D_ + (size_t)b * D_ + n]
                    + g_qpart[(size_t)3 * B_ * D_ + (size_t)b * D_ + n];
            qb_s[tid] = q;
            wc_s[tid] = Wc[n];
            vw_s[tid] = Vw[n];
        }

        float acc[4][4][4];
        #pragma unroll
        for (int i = 0; i < 4; ++i)
            #pragma unroll
            for (int j = 0; j < 4; ++j)
                #pragma unroll
                for (int r = 0; r < 4; ++r) acc[i][j][r] = 0.0f;

        ISSUE_CHUNK(0, 0, ns);
        ISSUE_CHUNK(1, 1, ns);

        for (int c = 0; c < 32; ++c) {
            if (c + 1 < 32) CP_WAIT1; else CP_WAIT0;   // chunk c resident
            __syncthreads();
            if (c + 2 < 32) ISSUE_CHUNK(c + 2, (c + 2) % NSTAGE, ns);

            const uint32_t bb = sb + (c % NSTAGE) * BUF_B;
            #pragma unroll
            for (int kk = 0; kk < 32; kk += 16) {
                const uint32_t xm = kk ? 0x20u : 0u;
                uint32_t af[4][4], bf0[2][4], bf1[2][4];
                // A_hi batch
                #pragma unroll
                for (int mf = 0; mf < 4; ++mf) ldsm4(af[mf], (bb + aoff[mf]) ^ xm);
                // B_hi batch
                #pragma unroll
                for (int p = 0; p < 2; ++p) ldsm4(bf0[p], (bb + boff[p]) ^ xm);
                // hh
                #pragma unroll
                for (int mf = 0; mf < 4; ++mf)
                    #pragma unroll
                    for (int p = 0; p < 2; ++p) {
                        mma16816(acc[mf][2 * p],     af[mf], bf0[p][0], bf0[p][2]);
                        mma16816(acc[mf][2 * p + 1], af[mf], bf0[p][1], bf0[p][3]);
                    }
                // B_lo batch
                #pragma unroll
                for (int p = 0; p < 2; ++p) ldsm4(bf1[p], (bb + boff[p] + 8192) ^ xm);
                // hl
                #pragma unroll
                for (int mf = 0; mf < 4; ++mf)
                    #pragma unroll
                    for (int p = 0; p < 2; ++p) {
                        mma16816(acc[mf][2 * p],     af[mf], bf1[p][0], bf1[p][2]);
                        mma16816(acc[mf][2 * p + 1], af[mf], bf1[p][1], bf1[p][3]);
                    }
                // A_lo batch (overwrite af)
                #pragma unroll
                for (int mf = 0; mf < 4; ++mf) ldsm4(af[mf], (bb + aoff[mf] + O_AL) ^ xm);
                // lh
                #pragma unroll
                for (int mf = 0; mf < 4; ++mf)
                    #pragma unroll
                    for (int p = 0; p < 2; ++p) {
                        mma16816(acc[mf][2 * p],     af[mf], bf0[p][0], bf0[p][2]);
                        mma16816(acc[mf][2 * p + 1], af[mf], bf0[p][1], bf0[p][3]);
                    }
            }
        }

        // fused epilogue for this subtile
        #pragma unroll
        for (int mf = 0; mf < 4; ++mf) {
            const int rA = wm + mf * 16 + (lane >> 2);
            const float pA = pc_s[rA], pB = pc_s[rA + 8];
            float sA = 0.f, sB = 0.f;
            #pragma unroll
            for (int nf = 0; nf < 4; ++nf) {
                int c0 = wn + nf * 8 + 2 * (lane & 3);
                int c1 = c0 + 1;
                sA += tanhf(acc[mf][nf][0] + qb_s[c0] + pA * wc_s[c0]) * vw_s[c0];
                sA += tanhf(acc[mf][nf][1] + qb_s[c1] + pA * wc_s[c1]) * vw_s[c1];
                sB += tanhf(acc[mf][nf][2] + qb_s[c0] + pB * wc_s[c0]) * vw_s[c0];
                sB += tanhf(acc[mf][nf][3] + qb_s[c1] + pB * wc_s[c1]) * vw_s[c1];
            }
            sacc[mf][0] += sA;
            sacc[mf][1] += sB;
        }
        __syncthreads();   // before next subtile overwrites qb_s/wc_s/vw_s
    }

    // reduce over lanes (n quads) and warps (n-warps), write final scores
    #pragma unroll
    for (int mf = 0; mf < 4; ++mf) {
        float sA = sacc[mf][0], sB = sacc[mf][1];
        sA += __shfl_xor_sync(0xffffffff, sA, 1);
        sA += __shfl_xor_sync(0xffffffff, sA, 2);
        sB += __shfl_xor_sync(0xffffffff, sB, 1);
        sB += __shfl_xor_sync(0xffffffff, sB, 2);
        if ((lane & 3) == 0) {
            int rA = wm + mf * 16 + (lane >> 2);
            Red[rA][wid & 3]     = sA;
            Red[rA + 8][wid & 3] = sB;
        }
    }
    __syncthreads();
    if (tid < 128) {
        g_score[(size_t)m0 + tid] = Red[tid][0] + Red[tid][1] + Red[tid][2] + Red[tid][3];
    }
}

// ============================================================================
// softmax over T per batch; writes attention_weights + coverage
// ============================================================================
__global__ void softmax_kernel(const float* __restrict__ prev_cov,
                               const float* __restrict__ Vb,
                               float* __restrict__ out) {
    __shared__ float sc[T_];
    __shared__ float red[256];
    const int b = blockIdx.x;
    const int tid = threadIdx.x;
    const float vb = Vb[0];

    float lmax = -1e30f;
    for (int t = tid; t < T_; t += 256) {
        float s = g_score[(size_t)b * T_ + t] + vb;
        sc[t] = s;
        lmax = fmaxf(lmax, s);
    }
    red[tid] = lmax;
    __syncthreads();
    for (int st = 128; st > 0; st >>= 1) {
        if (tid < st) red[tid] = fmaxf(red[tid], red[tid + st]);
        __syncthreads();
    }
    const float mx = red[0];
    __syncthreads();

    float lsum = 0.0f;
    for (int t = tid; t < T_; t += 256) {
        float e = expf(sc[t] - mx);
        sc[t] = e;
        lsum += e;
    }
    red[tid] = lsum;
    __syncthreads();
    for (int st = 128; st > 0; st >>= 1) {
        if (tid < st) red[tid] += red[tid + st];
        __syncthreads();
    }
    const float inv = 1.0f / red[0];

    float* aw_out  = out + B_ * D_;
    float* cov_out = out + B_ * D_ + B_ * T_;
    const float* pc = prev_cov + (size_t)b * T_;
    for (int t = tid; t < T_; t += 256) {
        float a = sc[t] * inv;
        aw_out[(size_t)b * T_ + t]  = a;
        cov_out[(size_t)b * T_ + t] = a + pc[t];
    }
}

// ============================================================================
// context partials + reduce
// ============================================================================
__global__ void ctx_part_kernel(const float* __restrict__ values,
                                const float* __restrict__ aw) {
    const int tc = blockIdx.x, b = blockIdx.y, tid = threadIdx.x;
    __shared__ float sa[128];
    const int t0 = tc * 128;
    if (tid < 128) sa[tid] = aw[(size_t)b * T_ + t0 + tid];
    __syncthreads();

    const float4* vp = (const float4*)(values) + ((size_t)b * T_ + t0) * (D_ / 4) + tid;
    float4 acc = make_float4(0.f, 0.f, 0.f, 0.f);
    #pragma unroll 4
    for (int t = 0; t < 128; ++t) {
        float4 v = vp[(size_t)t * (D_ / 4)];
        float a = sa[t];
        acc.x = fmaf(a, v.x, acc.x);
        acc.y = fmaf(a, v.y, acc.y);
        acc.z = fmaf(a, v.z, acc.z);
        acc.w = fmaf(a, v.w, acc.w);
    }
    ((float4*)g_ctxpart)[((size_t)tc * B_ + b) * (D_ / 4) + tid] = acc;
}

__global__ void ctx_reduce_kernel(float* __restrict__ out) {
    int g = blockIdx.x * blockDim.x + threadIdx.x;
    float s = 0.0f;
    #pragma unroll
    for (int tc = 0; tc < NCTX; ++tc)
        s += g_ctxpart[(size_t)tc * B_ * D_ + g];
    out[g] = s;
}

// ============================================================================
extern "C" void kernel_launch(void* const* d_in, const int* in_sizes, int n_in,
                              void* d_out, int out_size) {
    const float* query    = (const float*)d_in[0];
    const float* values   = (const float*)d_in[1];
    const float* prev_cov = (const float*)d_in[2];
    const float* Wh       = (const float*)d_in[3];
    const float* bh       = (const float*)d_in[4];
    const float* Ws       = (const float*)d_in[5];
    const float* bs       = (const float*)d_in[6];
    const float* Wc       = (const float*)d_in[7];
    const float* bc       = (const float*)d_in[8];
    const float* Vw       = (const float*)d_in[9];
    const float* Vb       = (const float*)d_in[10];
    float* out = (float*)d_out;

    cudaFuncSetAttribute(score_gemm_kernel,
                         cudaFuncAttributeMaxDynamicSharedMemorySize, GEMM_SMEM);

    conv_values_kernel<<<(int)((size_t)M_ * D_ / 4 / 256), 256>>>(values);
    conv_ws_kernel<<<dim3(32, 32), dim3(32, 8)>>>(Ws);
    qproj_part_kernel<<<dim3(128, KS_), 256>>>(query, Wh, bh, bs, bc);
    score_gemm_kernel<<<M_ / 128, 256, GEMM_SMEM>>>(prev_cov, Wc, Vw);
    softmax_kernel<<<B_, 256>>>(prev_cov, Vb, out);
    ctx_part_kernel<<<dim3(NCTX, B_), 256>>>(values, out + B_ * D_);
    ctx_reduce_kernel<<<(B_ * D_) / 256, 256>>>(out);
}